// round 1
// baseline (speedup 1.0000x reference)
#include <cuda_runtime.h>

// DenseWarpLayer: out[n,h,w,c] = bilinear(image, qy = h - flow[n,h,w,0],
//                                                qx = w - flow[n,h,w,1])
// with floor clamped to [0, size-2] and alphas clamped to [0,1]
// (faithful port of tfa.image.dense_image_warp).
//
// Shapes fixed by the dataset: N=8, H=512, W=512, C=32 (fp32).
// One thread handles one float4 (4 channels) of one output pixel.

#define N_ 8
#define H_ 512
#define W_ 512
#define C4_ 8   // 32 channels / 4 per float4

__global__ __launch_bounds__(256)
void dense_warp_kernel(const float* __restrict__ image,
                       const float* __restrict__ flow,
                       float* __restrict__ out)
{
    // total threads = N*H*W*C4 = 16,777,216 — exact grid, no bounds check needed
    unsigned tid = blockIdx.x * 256u + threadIdx.x;

    const unsigned c4  = tid & 7u;          // channel quad 0..7
    const unsigned pix = tid >> 3;          // linear (n,h,w)
    const unsigned w   = pix & (W_ - 1);
    const unsigned h   = (pix >> 9) & (H_ - 1);
    // n = pix >> 18 (not needed separately; pix already encodes it linearly)

    // flow for this pixel (same L1 line for all 8 threads of the pixel)
    const float2 fl = __ldg(reinterpret_cast<const float2*>(flow) + pix);

    const float qy = (float)h - fl.x;
    const float qx = (float)w - fl.y;

    float fyf = floorf(qy);
    float fxf = floorf(qx);
    fyf = fminf(fmaxf(fyf, 0.0f), (float)(H_ - 2));
    fxf = fminf(fmaxf(fxf, 0.0f), (float)(W_ - 2));

    const float ay = fminf(fmaxf(qy - fyf, 0.0f), 1.0f);
    const float ax = fminf(fmaxf(qx - fxf, 0.0f), 1.0f);

    const int iy = (int)fyf;
    const int ix = (int)fxf;

    // base index of (n, iy, ix, 0) in float4 units; n*H*W = pix - (h*W + w)... 
    // simpler: n = pix >> 18
    const unsigned n = pix >> 18;
    const long long rowbase = (((long long)n * H_ + iy) * W_ + ix) * C4_ + c4;

    const float4* img4 = reinterpret_cast<const float4*>(image);

    const float4 tl = __ldg(img4 + rowbase);
    const float4 tr = __ldg(img4 + rowbase + C4_);
    const float4 bl = __ldg(img4 + rowbase + (long long)W_ * C4_);
    const float4 br = __ldg(img4 + rowbase + (long long)W_ * C4_ + C4_);

    float4 r;
    {
        const float top_x = tl.x + ax * (tr.x - tl.x);
        const float bot_x = bl.x + ax * (br.x - bl.x);
        r.x = top_x + ay * (bot_x - top_x);

        const float top_y = tl.y + ax * (tr.y - tl.y);
        const float bot_y = bl.y + ax * (br.y - bl.y);
        r.y = top_y + ay * (bot_y - top_y);

        const float top_z = tl.z + ax * (tr.z - tl.z);
        const float bot_z = bl.z + ax * (br.z - bl.z);
        r.z = top_z + ay * (bot_z - top_z);

        const float top_w = tl.w + ax * (tr.w - tl.w);
        const float bot_w = bl.w + ax * (br.w - bl.w);
        r.w = top_w + ay * (bot_w - top_w);
    }

    reinterpret_cast<float4*>(out)[(long long)pix * C4_ + c4] = r;
}

extern "C" void kernel_launch(void* const* d_in, const int* in_sizes, int n_in,
                              void* d_out, int out_size)
{
    const float* image = (const float*)d_in[0];
    const float* flow  = (const float*)d_in[1];
    float* out = (float*)d_out;

    // N*H*W*C4 = 8*512*512*8 = 16,777,216 threads; 256/block -> 65,536 blocks
    dense_warp_kernel<<<65536, 256>>>(image, flow, out);
}